// round 9
// baseline (speedup 1.0000x reference)
#include <cuda_runtime.h>
#include <cuda_fp16.h>
#include <math.h>
#include <stdint.h>

#define B_ 256
#define D_ 128
#define C_ 100000
#define BC_ (B_ * C_)
#define SCALE_F 35.0f

// ---------------- device globals (scratch; no allocs allowed) ---------------
__device__ float  g_invF[B_];
__device__ __half g_fhi[B_ * D_];
__device__ __half g_flo[B_ * D_];

// ---------------- SMEM layout (bytes, dynamic) ------------------------------
// Per-CTA: 98 KB -> 2 CTAs/SM (228 KB carveout).
#define OFF_INVF 0                    // 256 floats
#define OFF_INVW 1024                 // 128 floats
#define OFF_A_HI 2048                 // 128 rows x 256B = 32 KB  (current batch half)
#define OFF_A_LO (OFF_A_HI + 32768)
#define OFF_B_HI (OFF_A_LO + 32768)   // 128 rows x 256B = 32 KB
#define SMEM_TOTAL (OFF_B_HI + 32768) // 100352 B

// ---------------- PTX helpers (portable sm_80+) ------------------------------
__device__ __forceinline__ uint32_t smem_u32(const void* p) {
    uint32_t a;
    asm("{ .reg .u64 t; cvta.to.shared.u64 t, %1; cvt.u32.u64 %0, t; }" : "=r"(a) : "l"(p));
    return a;
}
__device__ __forceinline__ void ldsm4(uint32_t* r, uint32_t addr) {
    asm volatile("ldmatrix.sync.aligned.m8n8.x4.shared.b16 {%0,%1,%2,%3}, [%4];"
                 : "=r"(r[0]), "=r"(r[1]), "=r"(r[2]), "=r"(r[3]) : "r"(addr));
}
__device__ __forceinline__ void mma_f16(float* d, const uint32_t* a,
                                        uint32_t b0, uint32_t b1) {
    asm volatile("mma.sync.aligned.m16n8k16.row.col.f32.f16.f16.f32 "
                 "{%0,%1,%2,%3}, {%4,%5,%6,%7}, {%8,%9}, {%0,%1,%2,%3};"
                 : "+f"(d[0]), "+f"(d[1]), "+f"(d[2]), "+f"(d[3])
                 : "r"(a[0]), "r"(a[1]), "r"(a[2]), "r"(a[3]), "r"(b0), "r"(b1));
}

// ---------------------------------------------------------------------------
// Kernel 1: feature prep — invF + fp16 hi/lo split. 32 blocks x 256 thr.
// ---------------------------------------------------------------------------
__global__ void prep_feat_kernel(const float* __restrict__ feat) {
    int warp = threadIdx.x >> 5, lane = threadIdx.x & 31;
    int row = blockIdx.x * 8 + warp;
    float4 v = *reinterpret_cast<const float4*>(&feat[row * D_ + lane * 4]);
    float s = v.x * v.x + v.y * v.y + v.z * v.z + v.w * v.w;
    #pragma unroll
    for (int o = 16; o > 0; o >>= 1) s += __shfl_xor_sync(0xffffffffu, s, o);

    __half2 h0 = __floats2half2_rn(v.x, v.y);
    __half2 h1 = __floats2half2_rn(v.z, v.w);
    __half2 l0 = __floats2half2_rn(v.x - __half2float(h0.x), v.y - __half2float(h0.y));
    __half2 l1 = __floats2half2_rn(v.z - __half2float(h1.x), v.w - __half2float(h1.y));
    *reinterpret_cast<uint2*>(&g_fhi[row * D_ + lane * 4]) =
        make_uint2(*reinterpret_cast<uint32_t*>(&h0), *reinterpret_cast<uint32_t*>(&h1));
    *reinterpret_cast<uint2*>(&g_flo[row * D_ + lane * 4]) =
        make_uint2(*reinterpret_cast<uint32_t*>(&l0), *reinterpret_cast<uint32_t*>(&l1));
    if (lane == 0) g_invF[row] = rsqrtf(s);
}

// ---------------------------------------------------------------------------
// Kernel 2: HMMA GEMM + epilogue, 2 CTAs/SM. One CTA per 128-class tile.
// Batch processed in two 128-row halves; half-1 restaged (L2-hot) while
// half-0 epilogue stores stream out. 8 warps 4(m)x2(n), warp tile 32x64.
// ---------------------------------------------------------------------------
__global__ __launch_bounds__(256, 2)
void arcface_hmma_kernel(const float* __restrict__ w, float* __restrict__ out) {
    extern __shared__ char smem[];
    const uint32_t sb = smem_u32(smem);
    const int tid = threadIdx.x, warp = tid >> 5, lane = tid & 31;
    const int wm = warp >> 1, wn = warp & 1;
    const int cbase = blockIdx.x * 128;

    // ---- stage invF -------------------------------------------------------
    *reinterpret_cast<float*>(smem + OFF_INVF + tid * 4) = g_invF[tid];

    // ---- stage A half 0: thread role (row = tid&127, hi/lo = tid>>7) ------
    {
        int row = tid & 127, which = tid >> 7;
        const __half* src = (which ? g_flo : g_fhi) + row * D_;
        char* dstbase = smem + (which ? OFF_A_LO : OFF_A_HI);
        const uint4* sp = reinterpret_cast<const uint4*>(src);
        uint32_t rb = (uint32_t)row * 256u, rx = (uint32_t)(row & 7);
        #pragma unroll
        for (int c = 0; c < 16; c++)
            *reinterpret_cast<uint4*>(dstbase + rb + (((uint32_t)c ^ rx) << 4)) = sp[c];
    }

    // ---- stage W tile (fp16 hi) + per-class inv norms ---------------------
    {
        int r = tid >> 1, half = tid & 1;
        int cg = cbase + r; if (cg >= C_) cg = C_ - 1;
        const float4* wr = reinterpret_cast<const float4*>(w + (size_t)cg * D_ + half * 64);
        uint32_t rb = (uint32_t)r * 256u, rx = (uint32_t)(r & 7);
        float s = 0.f;
        #pragma unroll
        for (int i = 0; i < 8; i++) {
            float4 v0 = wr[2 * i], v1 = wr[2 * i + 1];
            s += v0.x * v0.x + v0.y * v0.y + v0.z * v0.z + v0.w * v0.w;
            s += v1.x * v1.x + v1.y * v1.y + v1.z * v1.z + v1.w * v1.w;
            __half2 h0 = __floats2half2_rn(v0.x, v0.y);
            __half2 h1 = __floats2half2_rn(v0.z, v0.w);
            __half2 h2 = __floats2half2_rn(v1.x, v1.y);
            __half2 h3 = __floats2half2_rn(v1.z, v1.w);
            uint32_t chunk = (uint32_t)(half * 8 + i);
            *reinterpret_cast<uint4*>(smem + OFF_B_HI + rb + ((chunk ^ rx) << 4)) =
                make_uint4(*reinterpret_cast<uint32_t*>(&h0), *reinterpret_cast<uint32_t*>(&h1),
                           *reinterpret_cast<uint32_t*>(&h2), *reinterpret_cast<uint32_t*>(&h3));
        }
        s += __shfl_xor_sync(0xffffffffu, s, 1);
        if (half == 0) *reinterpret_cast<float*>(smem + OFF_INVW + r * 4) = rsqrtf(s);
    }

    __syncthreads();

    // ---- ldmatrix lane->address maps (validated R6/R7) --------------------
    const int a_row_in = lane & 15;
    const uint32_t a_sel = (uint32_t)(lane >> 4);
    const int b_cls_in = ((lane >> 4) << 3) | (lane & 7);
    const uint32_t b_sel = (uint32_t)((lane >> 3) & 1);

    uint32_t aAddrH[2], aAddrL[2], arx[2];
    #pragma unroll
    for (int fm = 0; fm < 2; fm++) {
        int arow = wm * 32 + fm * 16 + a_row_in;       // within 128-row half
        aAddrH[fm] = sb + OFF_A_HI + (uint32_t)arow * 256u;
        aAddrL[fm] = sb + OFF_A_LO + (uint32_t)arow * 256u;
        arx[fm] = (uint32_t)(arow & 7);
    }
    uint32_t bAddr[4], brx[4];
    #pragma unroll
    for (int j2 = 0; j2 < 4; j2++) {
        int brow = wn * 64 + j2 * 16 + b_cls_in;
        bAddr[j2] = sb + OFF_B_HI + (uint32_t)brow * 256u;
        brx[j2] = (uint32_t)(brow & 7);
    }

    const int g = lane >> 2, t2 = (lane & 3) * 2;
    float* out_cos = out;
    float* out_mrg = out + BC_;
    float* out_ip  = out + 2 * BC_;

    #pragma unroll 1
    for (int h = 0; h < 2; h++) {
        float d[2][8][4];
        #pragma unroll
        for (int fm = 0; fm < 2; fm++)
            #pragma unroll
            for (int jn = 0; jn < 8; jn++)
                #pragma unroll
                for (int q = 0; q < 4; q++) d[fm][jn][q] = 0.f;

        // ---- mainloop: B loaded once per kk, hi + lo passes ---------------
        #pragma unroll
        for (int kk = 0; kk < 8; kk++) {
            uint32_t b[4][4];
            #pragma unroll
            for (int j2 = 0; j2 < 4; j2++) {
                uint32_t chunk = (uint32_t)kk * 2u + b_sel;
                ldsm4(b[j2], bAddr[j2] + ((chunk ^ brx[j2]) << 4));
            }
            uint32_t a[2][4];
            #pragma unroll
            for (int fm = 0; fm < 2; fm++) {
                uint32_t chunk = (uint32_t)kk * 2u + a_sel;
                ldsm4(a[fm], aAddrH[fm] + ((chunk ^ arx[fm]) << 4));
            }
            #pragma unroll
            for (int fm = 0; fm < 2; fm++)
                #pragma unroll
                for (int jn = 0; jn < 8; jn++)
                    mma_f16(d[fm][jn], a[fm],
                            b[jn >> 1][(jn & 1) * 2], b[jn >> 1][(jn & 1) * 2 + 1]);
            #pragma unroll
            for (int fm = 0; fm < 2; fm++) {
                uint32_t chunk = (uint32_t)kk * 2u + a_sel;
                ldsm4(a[fm], aAddrL[fm] + ((chunk ^ arx[fm]) << 4));
            }
            #pragma unroll
            for (int fm = 0; fm < 2; fm++)
                #pragma unroll
                for (int jn = 0; jn < 8; jn++)
                    mma_f16(d[fm][jn], a[fm],
                            b[jn >> 1][(jn & 1) * 2], b[jn >> 1][(jn & 1) * 2 + 1]);
        }

        // All warps done reading this half's A tile.
        __syncthreads();

        // ---- restage A half 1 (issued before epilogue stores; L2-hot) ----
        if (h == 0) {
            int row = tid & 127, which = tid >> 7;
            const __half* src = (which ? g_flo : g_fhi) + (128 + row) * D_;
            char* dstbase = smem + (which ? OFF_A_LO : OFF_A_HI);
            const uint4* sp = reinterpret_cast<const uint4*>(src);
            uint32_t rb = (uint32_t)row * 256u, rx = (uint32_t)(row & 7);
            #pragma unroll
            for (int c = 0; c < 16; c++)
                *reinterpret_cast<uint4*>(dstbase + rb + (((uint32_t)c ^ rx) << 4)) = sp[c];
        }

        // ---- epilogue for this half (streaming stores) --------------------
        #pragma unroll
        for (int fm = 0; fm < 2; fm++) {
            int bat0 = h * 128 + wm * 32 + fm * 16 + g;
            float if0 = *reinterpret_cast<float*>(smem + OFF_INVF + bat0 * 4);
            float if1 = *reinterpret_cast<float*>(smem + OFF_INVF + (bat0 + 8) * 4);
            size_t ro0 = (size_t)bat0 * C_;
            size_t ro1 = (size_t)(bat0 + 8) * C_;
            #pragma unroll
            for (int jn = 0; jn < 8; jn++) {
                int cl = wn * 64 + jn * 8 + t2;
                int cls = cbase + cl;
                if (cls < C_) {
                    float2 iw = *reinterpret_cast<float2*>(smem + OFF_INVW + cl * 4);
                    float ip0 = d[fm][jn][0], ip1 = d[fm][jn][1];
                    float ip2 = d[fm][jn][2], ip3 = d[fm][jn][3];
                    float c0 = ip0 * if0 * iw.x, c1 = ip1 * if0 * iw.y;
                    float c2 = ip2 * if1 * iw.x, c3 = ip3 * if1 * iw.y;
                    __stcs(reinterpret_cast<float2*>(&out_ip[ro0 + cls]),  make_float2(ip0, ip1));
                    __stcs(reinterpret_cast<float2*>(&out_ip[ro1 + cls]),  make_float2(ip2, ip3));
                    __stcs(reinterpret_cast<float2*>(&out_cos[ro0 + cls]), make_float2(c0, c1));
                    __stcs(reinterpret_cast<float2*>(&out_cos[ro1 + cls]), make_float2(c2, c3));
                    __stcs(reinterpret_cast<float2*>(&out_mrg[ro0 + cls]),
                           make_float2(SCALE_F * c0, SCALE_F * c1));
                    __stcs(reinterpret_cast<float2*>(&out_mrg[ro1 + cls]),
                           make_float2(SCALE_F * c2, SCALE_F * c3));
                }
            }
        }

        if (h == 0) __syncthreads();   // A half-1 visible before mainloop 1
    }
}

// ---------------------------------------------------------------------------
// Kernel 3: ground-truth margin fixup (256 entries), float math.
// ---------------------------------------------------------------------------
__global__ void fix_gt_kernel(const int* __restrict__ lab_raw,
                              const float* __restrict__ out_cos,
                              float* __restrict__ out_mrg) {
    __shared__ int s_is64;
    int tid = threadIdx.x;
    if (tid == 0) s_is64 = 1;
    __syncthreads();
    if (tid < 128 && lab_raw[2 * tid + 1] != 0) atomicExch(&s_is64, 0);
    __syncthreads();

    int c = s_is64 ? lab_raw[2 * tid] : lab_raw[tid];
    size_t idx = (size_t)tid * C_ + c;
    float cg = out_cos[idx];

    float x = fminf(fmaxf(cg, -1.0f), 1.0f);
    const float thresh = -0.87758256189037271612f;     // -cos(0.5)
    float m;
    if (cg > thresh) m = cosf(acosf(x) + 0.5f);
    else             m = x - 0.5f * 0.47942553860420300027f;  // x - 0.5*sin(0.5)
    out_mrg[idx] = SCALE_F * m;
}

// ---------------------------------------------------------------------------
extern "C" void kernel_launch(void* const* d_in, const int* in_sizes, int n_in,
                              void* d_out, int out_size) {
    const float* feat = (const float*)d_in[0];
    const float* w    = (const float*)d_in[1];
    const int*   lab  = (const int*)d_in[2];
    float* out = (float*)d_out;

    prep_feat_kernel<<<32, 256>>>(feat);

    cudaFuncSetAttribute(arcface_hmma_kernel,
                         cudaFuncAttributeMaxDynamicSharedMemorySize, SMEM_TOTAL);
    int ntiles = (C_ + 127) / 128;   // 782
    arcface_hmma_kernel<<<ntiles, 256, SMEM_TOTAL>>>(w, out);

    fix_gt_kernel<<<1, 256>>>(lab, out, out + BC_);
}